// round 14
// baseline (speedup 1.0000x reference)
#include <cuda_runtime.h>
#include <cuda_fp16.h>
#include <cstdint>

#define NODES 50000
#define NPAD  50048            // 391 * 128
#define NEDGE 600000
#define DIM   128
#define EPSV  1e-5f

#define SA 36                  // As row stride (floats), conflict-free for ldmatrix
#define SW 136                 // Ws row stride (floats), conflict-free for b-fragment LDS

// ---------------- scratch (static device globals; no allocations) ----------
__device__ float  g_bufA[NPAD * DIM];   // fp32 agg output -> GEMM A (rows >= NODES stay 0)
__device__ __half g_h16a[NPAD * DIM];   // fp16 gather input (x scaled, then gemm2 out)
__device__ __half g_h16b[NPAD * DIM];   // fp16 gemm1 out
__device__ int    g_cnt[NODES];         // zero at load; prep re-zeroes every launch
__device__ int    g_off[NODES + 1];
__device__ int    g_pos[NODES];
__device__ int    g_csr[NEDGE];
__device__ int    g_bsum[64];
__device__ float  g_dinvA[NODES];       // rsqrt(deg+3)  (fill = 2, layers 1,2)
__device__ float  g_dinvB[NODES];       // rsqrt(deg+2)  (fill = 1, layer 3)

// ---------------- CSR build -------------------------------------------------
// edge_index is int32 (JAX x64 disabled downcasts int64 -> int32)
__global__ void count_deg_kernel(const int* __restrict__ ei) {
    int i = blockIdx.x * blockDim.x + threadIdx.x;
    if (i < NEDGE) atomicAdd(&g_cnt[ei[NEDGE + i]], 1);
}

// 49 blocks x 1024: block-local exclusive scan -> g_off, block totals -> g_bsum,
// per-node dinv factors, and the dinvA-prescaled fp16 copy of x.
__global__ void scan1_kernel(const float* __restrict__ x, __half* __restrict__ xs) {
    __shared__ int wsum[32];
    int tid = threadIdx.x, lane = tid & 31, wid = tid >> 5;
    int i = blockIdx.x * 1024 + tid;
    int v = (i < NODES) ? g_cnt[i] : 0;
    int s = v;
    #pragma unroll
    for (int m = 1; m < 32; m <<= 1) {
        int y = __shfl_up_sync(0xffffffffu, s, m);
        if (lane >= m) s += y;
    }
    if (lane == 31) wsum[wid] = s;
    __syncthreads();
    if (wid == 0) {
        int w = wsum[lane];
        #pragma unroll
        for (int m = 1; m < 32; m <<= 1) {
            int y = __shfl_up_sync(0xffffffffu, w, m);
            if (lane >= m) w += y;
        }
        wsum[lane] = w;
    }
    __syncthreads();
    int incl = s + (wid ? wsum[wid - 1] : 0);
    if (i < NODES) {
        g_off[i] = incl - v;                    // block-local exclusive
        float da = rsqrtf((float)(v + 3));
        g_dinvA[i] = da;
        g_dinvB[i] = rsqrtf((float)(v + 2));
        // prescale row i of x by dinvA, store fp16
        const float4* xr = (const float4*)(x + i * DIM);
        __half2*      xo = (__half2*)(xs + i * DIM);
        #pragma unroll 8
        for (int c = 0; c < 32; c++) {
            float4 t = xr[c];
            xo[2 * c]     = __floats2half2_rn(t.x * da, t.y * da);
            xo[2 * c + 1] = __floats2half2_rn(t.z * da, t.w * da);
        }
    }
    if (tid == 1023) g_bsum[blockIdx.x] = incl;
}

// 49 blocks x 1024: warp-parallel block-base reduction, then offsets + re-zero
__global__ void prep_kernel() {
    __shared__ int sbase;
    int tid = threadIdx.x, lane = tid & 31;
    int b = blockIdx.x;
    if (tid < 32) {
        int s = (lane < b) ? g_bsum[lane] : 0;
        if (lane + 32 < b) s += g_bsum[lane + 32];
        #pragma unroll
        for (int m = 16; m; m >>= 1) s += __shfl_xor_sync(0xffffffffu, s, m);
        if (lane == 0) {
            sbase = s;
            if (b == 0) g_off[NODES] = NEDGE;
        }
    }
    __syncthreads();
    int i = b * 1024 + tid;
    if (i < NODES) {
        int off = sbase + g_off[i];
        g_off[i] = off;
        g_pos[i] = off;
        g_cnt[i] = 0;
    }
}

__global__ void fill_csr_kernel(const int* __restrict__ ei) {
    int i = blockIdx.x * blockDim.x + threadIdx.x;
    if (i < NEDGE) {
        int s = ei[i];
        int d = ei[NEDGE + i];
        g_csr[atomicAdd(&g_pos[d], 1)] = s;
    }
}

// ---------------- aggregation: one warp/node, fp16 rows, HADD2 batch-4 ------
// input hs already scaled by dinv_layer per row (fp16):
// out[i] = dinv[i] * ( sum_{e: dst=i} hs[src_e] + k * hs[i] ),  k = 1 + fill
// Edges accumulated in fp16 (HADD2), flushed to fp32 every 4 edges.
__global__ void agg_kernel(const __half* __restrict__ hs,
                           float* __restrict__ o,
                           const float* __restrict__ dinv, float k)
{
    int w    = (blockIdx.x * blockDim.x + threadIdx.x) >> 5;
    int lane = threadIdx.x & 31;
    if (w >= NODES) return;

    int e0 = g_off[w], e1 = g_off[w + 1];
    const uint2* h2 = (const uint2*)hs;     // 4 halves per lane per row
    float4 a = make_float4(0.f, 0.f, 0.f, 0.f);
    const __half2 z2 = __float2half2_rn(0.f);

    int e = e0;
    for (; e + 4 <= e1; e += 4) {
        int s0 = g_csr[e],     s1 = g_csr[e + 1];
        int s2 = g_csr[e + 2], s3 = g_csr[e + 3];
        uint2 v0 = h2[s0 * 32 + lane];
        uint2 v1 = h2[s1 * 32 + lane];
        uint2 v2 = h2[s2 * 32 + lane];
        uint2 v3 = h2[s3 * 32 + lane];
        __half2 c0 = z2, c1 = z2;
        c0 = __hadd2(c0, *(__half2*)&v0.x); c1 = __hadd2(c1, *(__half2*)&v0.y);
        c0 = __hadd2(c0, *(__half2*)&v1.x); c1 = __hadd2(c1, *(__half2*)&v1.y);
        c0 = __hadd2(c0, *(__half2*)&v2.x); c1 = __hadd2(c1, *(__half2*)&v2.y);
        c0 = __hadd2(c0, *(__half2*)&v3.x); c1 = __hadd2(c1, *(__half2*)&v3.y);
        float2 f0 = __half22float2(c0);
        float2 f1 = __half22float2(c1);
        a.x += f0.x; a.y += f0.y; a.z += f1.x; a.w += f1.y;
    }
    if (e < e1) {
        __half2 c0 = z2, c1 = z2;
        for (; e < e1; e++) {
            int s = g_csr[e];
            uint2 v = h2[s * 32 + lane];
            c0 = __hadd2(c0, *(__half2*)&v.x);
            c1 = __hadd2(c1, *(__half2*)&v.y);
        }
        float2 f0 = __half22float2(c0);
        float2 f1 = __half22float2(c1);
        a.x += f0.x; a.y += f0.y; a.z += f1.x; a.w += f1.y;
    }

    float di = dinv[w];
    uint2 hv = h2[w * 32 + lane];
    float2 g0 = __half22float2(*(__half2*)&hv.x);
    float2 g1 = __half22float2(*(__half2*)&hv.y);
    float4 r;
    r.x = di * (a.x + k * g0.x);
    r.y = di * (a.y + k * g0.y);
    r.z = di * (a.z + k * g1.x);
    r.w = di * (a.w + k * g1.y);
    ((float4*)o)[w * 32 + lane] = r;
}

// ---------------- tf32 tensor-core GEMM + fused epilogue -------------------
__device__ __forceinline__ uint32_t f2tf(float x) {
    uint32_t r;
    asm("cvt.rna.tf32.f32 %0, %1;" : "=r"(r) : "f"(x));
    return r;
}

__device__ __forceinline__ void mma_tf32(float* c, const uint32_t* a,
                                         uint32_t b0, uint32_t b1) {
    asm volatile("mma.sync.aligned.m16n8k8.row.col.f32.tf32.tf32.f32 "
                 "{%0,%1,%2,%3}, {%4,%5,%6,%7}, {%8,%9}, {%0,%1,%2,%3};"
                 : "+f"(c[0]), "+f"(c[1]), "+f"(c[2]), "+f"(c[3])
                 : "r"(a[0]), "r"(a[1]), "r"(a[2]), "r"(a[3]),
                   "r"(b0), "r"(b1));
}

// Block: 128 rows x 128 cols, 8 warps each owning 16 full rows.
// MODE 0: out16 = (half)( scl[r] * relu(LN(A@W + bias)*gamma + beta) )
// MODE 1: out   = A@W + bias + resid   (fp32)
template<int MODE>
__global__ __launch_bounds__(256)
void gemm_tc_kernel(const float* __restrict__ A, const float* __restrict__ W,
                    const float* __restrict__ bias,
                    const float* __restrict__ gamma, const float* __restrict__ beta,
                    const float* __restrict__ resid, const float* __restrict__ scl,
                    float* __restrict__ out, __half* __restrict__ out16)
{
    __shared__ float As[128 * SA];
    __shared__ float Ws[32 * SW];

    const int tid  = threadIdx.x;
    const int warp = tid >> 5, lane = tid & 31;
    const int row0 = blockIdx.x * 128;

    const uint32_t* wsb = (const uint32_t*)Ws;
    uint32_t as_u32 = (uint32_t)__cvta_generic_to_shared(As);

    float acc[16][4];
    #pragma unroll
    for (int j = 0; j < 16; j++)
        #pragma unroll
        for (int c = 0; c < 4; c++) acc[j][c] = 0.f;

    const int m  = lane >> 3, rr = lane & 7;
    const int ar = warp * 16 + (m & 1) * 8 + rr;
    const int ac = (m >> 1) * 4;

    for (int kb = 0; kb < 4; kb++) {
        // A chunk: 128 x 32 -> tf32 smem
        #pragma unroll
        for (int u = 0; u < 4; u++) {
            int idx = tid + 256 * u;
            int r = idx >> 3, c4 = (idx & 7) << 2;
            float4 t = *(const float4*)&A[(row0 + r) * DIM + kb * 32 + c4];
            uint4 v = make_uint4(f2tf(t.x), f2tf(t.y), f2tf(t.z), f2tf(t.w));
            *(uint4*)&As[r * SA + c4] = v;
        }
        // W chunk: 32 x 128 -> tf32 smem (k-major)
        #pragma unroll
        for (int u = 0; u < 4; u++) {
            int idx = tid + 256 * u;
            int k = idx >> 5, n4 = (idx & 31) << 2;
            float4 t = *(const float4*)&W[(kb * 32 + k) * DIM + n4];
            uint4 v = make_uint4(f2tf(t.x), f2tf(t.y), f2tf(t.z), f2tf(t.w));
            *(uint4*)&Ws[k * SW + n4] = v;
        }
        __syncthreads();

        #pragma unroll
        for (int ks = 0; ks < 4; ks++) {
            uint32_t a[4];
            uint32_t addr = as_u32 + (uint32_t)(ar * SA + ks * 8 + ac) * 4u;
            asm volatile("ldmatrix.sync.aligned.m8n8.x4.shared.b16 "
                         "{%0,%1,%2,%3}, [%4];"
                         : "=r"(a[0]), "=r"(a[1]), "=r"(a[2]), "=r"(a[3])
                         : "r"(addr));
            const int kk = ks * 8 + (lane & 3);
            const int nn = lane >> 2;
            #pragma unroll
            for (int j = 0; j < 16; j++) {
                uint32_t b0 = wsb[kk * SW + j * 8 + nn];
                uint32_t b1 = wsb[(kk + 4) * SW + j * 8 + nn];
                mma_tf32(acc[j], a, b0, b1);
            }
        }
        __syncthreads();
    }

    // epilogue: row held by 4 consecutive lanes -> shfl_xor 1,2 reduces it
    const int rA = row0 + warp * 16 + (lane >> 2);
    const int cb = 2 * (lane & 3);
    const float2* bias2  = (const float2*)bias;
    const float2* gam2   = (const float2*)gamma;
    const float2* bet2   = (const float2*)beta;
    const float2* resid2 = (const float2*)resid;
    float2*  out2  = (float2*)out;
    __half2* out2h = (__half2*)out16;

    #pragma unroll
    for (int half = 0; half < 2; half++) {
        int r = rA + half * 8;
        float v[32];
        #pragma unroll
        for (int j = 0; j < 16; j++) {
            float2 bv = __ldg(&bias2[j * 4 + (lane & 3)]);
            v[2 * j]     = acc[j][half * 2]     + bv.x;
            v[2 * j + 1] = acc[j][half * 2 + 1] + bv.y;
        }
        if (MODE == 0) {
            float s = 0.f;
            #pragma unroll
            for (int e = 0; e < 32; e++) s += v[e];
            s += __shfl_xor_sync(0xffffffffu, s, 1);
            s += __shfl_xor_sync(0xffffffffu, s, 2);
            float mu = s * (1.0f / 128.0f);
            float s2 = 0.f;
            #pragma unroll
            for (int e = 0; e < 32; e++) { float d = v[e] - mu; s2 += d * d; }
            s2 += __shfl_xor_sync(0xffffffffu, s2, 1);
            s2 += __shfl_xor_sync(0xffffffffu, s2, 2);
            float rs = rsqrtf(s2 * (1.0f / 128.0f) + EPSV);
            if (r < NODES) {
                float sc = __ldg(&scl[r]);
                #pragma unroll
                for (int j = 0; j < 16; j++) {
                    float2 gv = __ldg(&gam2[j * 4 + (lane & 3)]);
                    float2 be = __ldg(&bet2[j * 4 + (lane & 3)]);
                    float ox = sc * fmaxf((v[2 * j]     - mu) * rs * gv.x + be.x, 0.f);
                    float oy = sc * fmaxf((v[2 * j + 1] - mu) * rs * gv.y + be.y, 0.f);
                    out2h[(r * DIM + j * 8 + cb) >> 1] = __floats2half2_rn(ox, oy);
                }
            }
        } else {
            if (r < NODES) {
                #pragma unroll
                for (int j = 0; j < 16; j++) {
                    float2 rv = __ldg(&resid2[(r * DIM + j * 8 + cb) >> 1]);
                    float2 o;
                    o.x = v[2 * j]     + rv.x;
                    o.y = v[2 * j + 1] + rv.y;
                    out2[(r * DIM + j * 8 + cb) >> 1] = o;
                }
            }
        }
    }
}

// ---------------- launch ----------------------------------------------------
extern "C" void kernel_launch(void* const* d_in, const int* in_sizes, int n_in,
                              void* d_out, int out_size)
{
    const float* x   = (const float*)d_in[0];
    const int*   ei  = (const int*)d_in[1];
    const float* W1 = (const float*)d_in[2];
    const float* b1 = (const float*)d_in[3];
    const float* g1 = (const float*)d_in[4];
    const float* be1= (const float*)d_in[5];
    const float* W2 = (const float*)d_in[6];
    const float* b2 = (const float*)d_in[7];
    const float* g2 = (const float*)d_in[8];
    const float* be2= (const float*)d_in[9];
    const float* W3 = (const float*)d_in[10];
    const float* b3 = (const float*)d_in[11];
    float* out = (float*)d_out;

    float*  bufA = nullptr;
    __half* h16a = nullptr;
    __half* h16b = nullptr;
    float*  dinvA = nullptr;
    float*  dinvB = nullptr;
    cudaGetSymbolAddress((void**)&bufA, g_bufA);
    cudaGetSymbolAddress((void**)&h16a, g_h16a);
    cudaGetSymbolAddress((void**)&h16b, g_h16b);
    cudaGetSymbolAddress((void**)&dinvA, g_dinvA);
    cudaGetSymbolAddress((void**)&dinvB, g_dinvB);

    const int TB = 256;
    dim3 eb((NEDGE + TB - 1) / TB);

    // CSR build + fp16 prescale of x (4 launches)
    count_deg_kernel<<<eb, TB>>>(ei);
    scan1_kernel<<<49, 1024>>>(x, h16a);          // scan + dinv + h16a = fp16(dinvA.*x)
    prep_kernel<<<49, 1024>>>();
    fill_csr_kernel<<<eb, TB>>>(ei);

    dim3 ab(NODES * 32 / TB);   // one warp per node
    dim3 gb(NPAD / 128);        // 391 blocks

    // layer 1 (fill = 2): gather fp16 x_scaled; gemm emits fp16 scaled by dinvA
    agg_kernel<<<ab, TB>>>(h16a, bufA, dinvA, 3.0f);
    gemm_tc_kernel<0><<<gb, TB>>>(bufA, W1, b1, g1, be1, nullptr, dinvA, nullptr, h16b);
    // layer 2 (fill = 2): gemm emits fp16 scaled by dinvB
    agg_kernel<<<ab, TB>>>(h16b, bufA, dinvA, 3.0f);
    gemm_tc_kernel<0><<<gb, TB>>>(bufA, W2, b2, g2, be2, nullptr, dinvB, nullptr, h16a);
    // layer 3 (fill = 1) + residual (fp32 out)
    agg_kernel<<<ab, TB>>>(h16a, bufA, dinvB, 2.0f);
    gemm_tc_kernel<1><<<gb, TB>>>(bufA, W3, b3, nullptr, nullptr, x, nullptr, out, nullptr);
}

// round 17
// speedup vs baseline: 1.6021x; 1.6021x over previous
#include <cuda_runtime.h>
#include <cstdint>

#define NODES 50000
#define NPAD  50048            // 391 * 128
#define NEDGE 600000
#define DIM   128
#define EPSV  1e-5f

#define SA 36                  // As row stride (floats), conflict-free for ldmatrix
#define SW 136                 // Ws row stride (floats), conflict-free for b-fragment LDS

// ---------------- scratch (static device globals; no allocations) ----------
__device__ float g_bufA[NPAD * DIM];   // agg outputs (rows >= NODES stay 0)
__device__ float g_bufB[NPAD * DIM];   // gemm1 output (scaled by dinvA)
__device__ float g_bufC[NPAD * DIM];   // x_scaled, later gemm2 output (scaled by dinvB)
__device__ int   g_cnt[NODES];         // zero at load; prep re-zeroes every launch
__device__ int   g_off[NODES + 1];
__device__ int   g_pos[NODES];
__device__ int   g_csr[NEDGE];
__device__ int   g_bsum[64];
__device__ float g_dinvA[NODES];       // rsqrt(deg+3)  (fill = 2, layers 1,2)
__device__ float g_dinvB[NODES];       // rsqrt(deg+2)  (fill = 1, layer 3)

// ---------------- CSR build -------------------------------------------------
// edge_index is int32 (JAX x64 disabled downcasts int64 -> int32)
__global__ void count_deg_kernel(const int* __restrict__ ei) {
    int i = blockIdx.x * blockDim.x + threadIdx.x;
    if (i < NEDGE) atomicAdd(&g_cnt[ei[NEDGE + i]], 1);
}

// 49 blocks x 1024: block-local exclusive scan -> g_off, block totals -> g_bsum,
// per-node dinv factors, and the dinvA-prescaled copy of x (bufC).
__global__ void scan1_kernel(const float* __restrict__ x, float* __restrict__ xs) {
    __shared__ int wsum[32];
    int tid = threadIdx.x, lane = tid & 31, wid = tid >> 5;
    int i = blockIdx.x * 1024 + tid;
    cudaGridDependencySynchronize();        // wait for count_deg (g_cnt)
    int v = (i < NODES) ? g_cnt[i] : 0;
    int s = v;
    #pragma unroll
    for (int m = 1; m < 32; m <<= 1) {
        int y = __shfl_up_sync(0xffffffffu, s, m);
        if (lane >= m) s += y;
    }
    if (lane == 31) wsum[wid] = s;
    __syncthreads();
    if (wid == 0) {
        int w = wsum[lane];
        #pragma unroll
        for (int m = 1; m < 32; m <<= 1) {
            int y = __shfl_up_sync(0xffffffffu, w, m);
            if (lane >= m) w += y;
        }
        wsum[lane] = w;
    }
    __syncthreads();
    int incl = s + (wid ? wsum[wid - 1] : 0);
    if (i < NODES) {
        g_off[i] = incl - v;                    // block-local exclusive
        float da = rsqrtf((float)(v + 3));
        g_dinvA[i] = da;
        g_dinvB[i] = rsqrtf((float)(v + 2));
        // prescale row i of x by dinvA
        const float4* xr = (const float4*)(x + i * DIM);
        float4*       xo = (float4*)(xs + i * DIM);
        #pragma unroll 8
        for (int c = 0; c < 32; c++) {
            float4 t = xr[c];
            t.x *= da; t.y *= da; t.z *= da; t.w *= da;
            xo[c] = t;
        }
    }
    if (tid == 1023) g_bsum[blockIdx.x] = incl;
}

// 49 blocks x 1024: warp-parallel block-base reduction, then offsets + re-zero
__global__ void prep_kernel() {
    __shared__ int sbase;
    int tid = threadIdx.x, lane = tid & 31;
    int b = blockIdx.x;
    cudaGridDependencySynchronize();        // wait for scan1 (g_bsum, g_off)
    if (tid < 32) {
        int s = (lane < b) ? g_bsum[lane] : 0;
        if (lane + 32 < b) s += g_bsum[lane + 32];
        #pragma unroll
        for (int m = 16; m; m >>= 1) s += __shfl_xor_sync(0xffffffffu, s, m);
        if (lane == 0) {
            sbase = s;
            if (b == 0) g_off[NODES] = NEDGE;
        }
    }
    __syncthreads();
    int i = b * 1024 + tid;
    if (i < NODES) {
        int off = sbase + g_off[i];
        g_off[i] = off;
        g_pos[i] = off;
        g_cnt[i] = 0;
    }
}

// Edge-index loads issued BEFORE the dependency sync (ei is a harness input):
// their L2/DRAM latency overlaps with prep's tail.
__global__ void fill_csr_kernel(const int* __restrict__ ei) {
    int i = blockIdx.x * blockDim.x + threadIdx.x;
    int s = 0, d = 0;
    bool act = (i < NEDGE);
    if (act) { s = ei[i]; d = ei[NEDGE + i]; }
    cudaGridDependencySynchronize();        // wait for prep (g_pos)
    if (act) g_csr[atomicAdd(&g_pos[d], 1)] = s;
}

// ---------------- aggregation: one warp/node, prescaled rows, 8-edge batch --
// input hs already scaled by dinv_layer per row:
// out[i] = dinv[i] * ( sum_{e: dst=i} hs[src_e] + k * hs[i] ),  k = 1 + fill
__global__ void agg_kernel(const float* __restrict__ hs,
                           float* __restrict__ o,
                           const float* __restrict__ dinv, float k)
{
    int w    = (blockIdx.x * blockDim.x + threadIdx.x) >> 5;
    int lane = threadIdx.x & 31;
    cudaGridDependencySynchronize();        // wait for upstream (csr / hs)
    if (w >= NODES) return;

    int e0 = g_off[w], e1 = g_off[w + 1];
    const float4* h4 = (const float4*)hs;
    float4 a = make_float4(0.f, 0.f, 0.f, 0.f);

    int e = e0;
    for (; e + 8 <= e1; e += 8) {
        int s0 = g_csr[e],     s1 = g_csr[e + 1];
        int s2 = g_csr[e + 2], s3 = g_csr[e + 3];
        int s4 = g_csr[e + 4], s5 = g_csr[e + 5];
        int s6 = g_csr[e + 6], s7 = g_csr[e + 7];
        float4 v0 = h4[s0 * 32 + lane];
        float4 v1 = h4[s1 * 32 + lane];
        float4 v2 = h4[s2 * 32 + lane];
        float4 v3 = h4[s3 * 32 + lane];
        float4 v4 = h4[s4 * 32 + lane];
        float4 v5 = h4[s5 * 32 + lane];
        float4 v6 = h4[s6 * 32 + lane];
        float4 v7 = h4[s7 * 32 + lane];
        a.x += v0.x; a.y += v0.y; a.z += v0.z; a.w += v0.w;
        a.x += v1.x; a.y += v1.y; a.z += v1.z; a.w += v1.w;
        a.x += v2.x; a.y += v2.y; a.z += v2.z; a.w += v2.w;
        a.x += v3.x; a.y += v3.y; a.z += v3.z; a.w += v3.w;
        a.x += v4.x; a.y += v4.y; a.z += v4.z; a.w += v4.w;
        a.x += v5.x; a.y += v5.y; a.z += v5.z; a.w += v5.w;
        a.x += v6.x; a.y += v6.y; a.z += v6.z; a.w += v6.w;
        a.x += v7.x; a.y += v7.y; a.z += v7.z; a.w += v7.w;
    }
    for (; e < e1; e++) {
        int s = g_csr[e];
        float4 v = h4[s * 32 + lane];
        a.x += v.x; a.y += v.y; a.z += v.z; a.w += v.w;
    }

    float di = dinv[w];
    float4 hv = h4[w * 32 + lane];
    float4 r;
    r.x = di * (a.x + k * hv.x);
    r.y = di * (a.y + k * hv.y);
    r.z = di * (a.z + k * hv.z);
    r.w = di * (a.w + k * hv.w);
    ((float4*)o)[w * 32 + lane] = r;
}

// ---------------- tf32 tensor-core GEMM + fused epilogue -------------------
__device__ __forceinline__ uint32_t f2tf(float x) {
    uint32_t r;
    asm("cvt.rna.tf32.f32 %0, %1;" : "=r"(r) : "f"(x));
    return r;
}

__device__ __forceinline__ void mma_tf32(float* c, const uint32_t* a,
                                         uint32_t b0, uint32_t b1) {
    asm volatile("mma.sync.aligned.m16n8k8.row.col.f32.tf32.tf32.f32 "
                 "{%0,%1,%2,%3}, {%4,%5,%6,%7}, {%8,%9}, {%0,%1,%2,%3};"
                 : "+f"(c[0]), "+f"(c[1]), "+f"(c[2]), "+f"(c[3])
                 : "r"(a[0]), "r"(a[1]), "r"(a[2]), "r"(a[3]),
                   "r"(b0), "r"(b1));
}

// Block: 128 rows x 128 cols, 8 warps each owning 16 full rows.
// First W chunk is staged into smem BEFORE the dependency sync (W is an input).
// MODE 0: out = scl[r] * relu(LN(A@W + bias) * gamma + beta)   (scl = next layer's dinv)
// MODE 1: out = A@W + bias + resid
template<int MODE>
__global__ __launch_bounds__(256)
void gemm_tc_kernel(const float* __restrict__ A, const float* __restrict__ W,
                    const float* __restrict__ bias,
                    const float* __restrict__ gamma, const float* __restrict__ beta,
                    const float* __restrict__ resid, const float* __restrict__ scl,
                    float* __restrict__ out)
{
    __shared__ float As[128 * SA];
    __shared__ float Ws[32 * SW];

    const int tid  = threadIdx.x;
    const int warp = tid >> 5, lane = tid & 31;
    const int row0 = blockIdx.x * 128;

    const uint32_t* wsb = (const uint32_t*)Ws;
    uint32_t as_u32 = (uint32_t)__cvta_generic_to_shared(As);

    float acc[16][4];
    #pragma unroll
    for (int j = 0; j < 16; j++)
        #pragma unroll
        for (int c = 0; c < 4; c++) acc[j][c] = 0.f;

    const int m  = lane >> 3, rr = lane & 7;
    const int ar = warp * 16 + (m & 1) * 8 + rr;
    const int ac = (m >> 1) * 4;

    for (int kb = 0; kb < 4; kb++) {
        // W chunk: 32 x 128 -> tf32 smem (k-major) — independent of upstream
        #pragma unroll
        for (int u = 0; u < 4; u++) {
            int idx = tid + 256 * u;
            int k = idx >> 5, n4 = (idx & 31) << 2;
            float4 t = *(const float4*)&W[(kb * 32 + k) * DIM + n4];
            uint4 v = make_uint4(f2tf(t.x), f2tf(t.y), f2tf(t.z), f2tf(t.w));
            *(uint4*)&Ws[k * SW + n4] = v;
        }
        if (kb == 0) cudaGridDependencySynchronize();   // wait for agg (A)
        // A chunk: 128 x 32 -> tf32 smem (dependent)
        #pragma unroll
        for (int u = 0; u < 4; u++) {
            int idx = tid + 256 * u;
            int r = idx >> 3, c4 = (idx & 7) << 2;
            float4 t = *(const float4*)&A[(row0 + r) * DIM + kb * 32 + c4];
            uint4 v = make_uint4(f2tf(t.x), f2tf(t.y), f2tf(t.z), f2tf(t.w));
            *(uint4*)&As[r * SA + c4] = v;
        }
        __syncthreads();

        #pragma unroll
        for (int ks = 0; ks < 4; ks++) {
            uint32_t a[4];
            uint32_t addr = as_u32 + (uint32_t)(ar * SA + ks * 8 + ac) * 4u;
            asm volatile("ldmatrix.sync.aligned.m8n8.x4.shared.b16 "
                         "{%0,%1,%2,%3}, [%4];"
                         : "=r"(a[0]), "=r"(a[1]), "=r"(a[2]), "=r"(a[3])
                         : "r"(addr));
            const int kk = ks * 8 + (lane & 3);
            const int nn = lane >> 2;
            #pragma unroll
            for (int j = 0; j < 16; j++) {
                uint32_t b0 = wsb[kk * SW + j * 8 + nn];
                uint32_t b1 = wsb[(kk + 4) * SW + j * 8 + nn];
                mma_tf32(acc[j], a, b0, b1);
            }
        }
        __syncthreads();
    }

    // epilogue: row held by 4 consecutive lanes -> shfl_xor 1,2 reduces it
    const int rA = row0 + warp * 16 + (lane >> 2);
    const int cb = 2 * (lane & 3);
    const float2* bias2  = (const float2*)bias;
    const float2* gam2   = (const float2*)gamma;
    const float2* bet2   = (const float2*)beta;
    const float2* resid2 = (const float2*)resid;
    float2* out2 = (float2*)out;

    #pragma unroll
    for (int half = 0; half < 2; half++) {
        int r = rA + half * 8;
        float v[32];
        #pragma unroll
        for (int j = 0; j < 16; j++) {
            float2 bv = __ldg(&bias2[j * 4 + (lane & 3)]);
            v[2 * j]     = acc[j][half * 2]     + bv.x;
            v[2 * j + 1] = acc[j][half * 2 + 1] + bv.y;
        }
        if (MODE == 0) {
            float s = 0.f;
            #pragma unroll
            for (int e = 0; e < 32; e++) s += v[e];
            s += __shfl_xor_sync(0xffffffffu, s, 1);
            s += __shfl_xor_sync(0xffffffffu, s, 2);
            float mu = s * (1.0f / 128.0f);
            float s2 = 0.f;
            #pragma unroll
            for (int e = 0; e < 32; e++) { float d = v[e] - mu; s2 += d * d; }
            s2 += __shfl_xor_sync(0xffffffffu, s2, 1);
            s2 += __shfl_xor_sync(0xffffffffu, s2, 2);
            float rs = rsqrtf(s2 * (1.0f / 128.0f) + EPSV);
            if (r < NODES) {
                float sc = __ldg(&scl[r]);
                #pragma unroll
                for (int j = 0; j < 16; j++) {
                    float2 gv = __ldg(&gam2[j * 4 + (lane & 3)]);
                    float2 be = __ldg(&bet2[j * 4 + (lane & 3)]);
                    float2 o;
                    o.x = sc * fmaxf((v[2 * j]     - mu) * rs * gv.x + be.x, 0.f);
                    o.y = sc * fmaxf((v[2 * j + 1] - mu) * rs * gv.y + be.y, 0.f);
                    out2[(r * DIM + j * 8 + cb) >> 1] = o;
                }
            }
        } else {
            if (r < NODES) {
                #pragma unroll
                for (int j = 0; j < 16; j++) {
                    float2 rv = __ldg(&resid2[(r * DIM + j * 8 + cb) >> 1]);
                    float2 o;
                    o.x = v[2 * j]     + rv.x;
                    o.y = v[2 * j + 1] + rv.y;
                    out2[(r * DIM + j * 8 + cb) >> 1] = o;
                }
            }
        }
    }
}

// ---------------- PDL launch helper -----------------------------------------
template <typename F, typename... Args>
static void launch_pdl(F f, dim3 grid, dim3 block, Args... args) {
    cudaLaunchConfig_t cfg = {};
    cfg.gridDim = grid;
    cfg.blockDim = block;
    cfg.dynamicSmemBytes = 0;
    cfg.stream = 0;
    cudaLaunchAttribute attr[1];
    attr[0].id = cudaLaunchAttributeProgrammaticStreamSerialization;
    attr[0].val.programmaticStreamSerializationAllowed = 1;
    cfg.attrs = attr;
    cfg.numAttrs = 1;
    cudaLaunchKernelEx(&cfg, f, args...);
}

// ---------------- launch ----------------------------------------------------
extern "C" void kernel_launch(void* const* d_in, const int* in_sizes, int n_in,
                              void* d_out, int out_size)
{
    const float* x   = (const float*)d_in[0];
    const int*   ei  = (const int*)d_in[1];
    const float* W1 = (const float*)d_in[2];
    const float* b1 = (const float*)d_in[3];
    const float* g1 = (const float*)d_in[4];
    const float* be1= (const float*)d_in[5];
    const float* W2 = (const float*)d_in[6];
    const float* b2 = (const float*)d_in[7];
    const float* g2 = (const float*)d_in[8];
    const float* be2= (const float*)d_in[9];
    const float* W3 = (const float*)d_in[10];
    const float* b3 = (const float*)d_in[11];
    float* out = (float*)d_out;

    float* bufA = nullptr;
    float* bufB = nullptr;
    float* bufC = nullptr;
    float* dinvA = nullptr;
    float* dinvB = nullptr;
    cudaGetSymbolAddress((void**)&bufA, g_bufA);
    cudaGetSymbolAddress((void**)&bufB, g_bufB);
    cudaGetSymbolAddress((void**)&bufC, g_bufC);
    cudaGetSymbolAddress((void**)&dinvA, g_dinvA);
    cudaGetSymbolAddress((void**)&dinvB, g_dinvB);

    const int TB = 256;
    dim3 tb(TB);
    dim3 eb((NEDGE + TB - 1) / TB);
    dim3 sb(49), sbt(1024);
    dim3 ab(NODES * 32 / TB);   // one warp per node
    dim3 gb(NPAD / 128);        // 391 blocks

    // CSR build + prescale (4 launches); count_deg launched normally,
    // everything after chains via PDL.
    count_deg_kernel<<<eb, tb>>>(ei);
    launch_pdl(scan1_kernel, sb, sbt, x, bufC);          // scan + dinv + bufC = dinvA.*x
    launch_pdl(prep_kernel, sb, sbt);
    launch_pdl(fill_csr_kernel, eb, tb, ei);

    // layer 1 (fill = 2): gather prescaled x, output scaled by dinvA for layer 2
    launch_pdl(agg_kernel, ab, tb, (const float*)bufC, bufA, (const float*)dinvA, 3.0f);
    launch_pdl(gemm_tc_kernel<0>, gb, tb,
               (const float*)bufA, W1, b1, g1, be1,
               (const float*)nullptr, (const float*)dinvA, bufB);
    // layer 2 (fill = 2): output scaled by dinvB for layer 3
    launch_pdl(agg_kernel, ab, tb, (const float*)bufB, bufA, (const float*)dinvA, 3.0f);
    launch_pdl(gemm_tc_kernel<0>, gb, tb,
               (const float*)bufA, W2, b2, g2, be2,
               (const float*)nullptr, (const float*)dinvB, bufC);
    // layer 3 (fill = 1) + residual
    launch_pdl(agg_kernel, ab, tb, (const float*)bufC, bufA, (const float*)dinvB, 2.0f);
    launch_pdl(gemm_tc_kernel<1>, gb, tb,
               (const float*)bufA, W3, b3,
               (const float*)nullptr, (const float*)nullptr,
               x, (const float*)nullptr, out);
}